// round 13
// baseline (speedup 1.0000x reference)
#include <cuda_runtime.h>
#include <cstdint>

// NodeDropout: out[e] = values[e] unless src or dst node dropped.
// smem 1-bit bitmask + LDS gathers (R6 win). R9: push bytes-in-flight —
// 16 edges/thread/iter (12 independent 16B streaming loads), 768 threads,
// streaming cache hints on the once-touched streams.

#define MAX_BIT_WORDS 65536  // supports up to 2,097,152 nodes
__device__ unsigned int g_bits[MAX_BIT_WORDS];

// ---- pre-kernel: pack flags (4-byte 0/nonzero) into bitmask via ballot ----
__global__ void pack_flags_kernel(const unsigned int* __restrict__ flags,
                                  int N, int nwords)
{
    int t = blockIdx.x * blockDim.x + threadIdx.x;
    int w = t >> 5;
    int lane = t & 31;
    if (w >= nwords) return;
    int idx = w * 32 + lane;
    unsigned int f = (idx < N) ? flags[idx] : 0u;
    unsigned int ballot = __ballot_sync(0xFFFFFFFFu, f != 0u);
    if (lane == 0) g_bits[w] = ballot;
}

__device__ __forceinline__ unsigned int bit_of(const unsigned int* bits, int i)
{
    return (bits[i >> 5] >> (i & 31)) & 1u;
}

__device__ __forceinline__ float4 mask4(const unsigned int* bits, int4 s, int4 d, float4 v)
{
    float4 r;
    r.x = (bit_of(bits, s.x) | bit_of(bits, d.x)) ? 0.0f : v.x;
    r.y = (bit_of(bits, s.y) | bit_of(bits, d.y)) ? 0.0f : v.y;
    r.z = (bit_of(bits, s.z) | bit_of(bits, d.z)) ? 0.0f : v.z;
    r.w = (bit_of(bits, s.w) | bit_of(bits, d.w)) ? 0.0f : v.w;
    return r;
}

// ---- main kernel: one CTA/SM, bitmask in smem, 16 edges/thread/iter ----
__global__ void __launch_bounds__(768, 1)
node_dropout_kernel(const int* __restrict__ ei,
                    const float* __restrict__ vals,
                    float* __restrict__ out,
                    int E, int nwords)
{
    extern __shared__ unsigned int bits[];
    for (int i = threadIdx.x; i < nwords; i += blockDim.x)
        bits[i] = g_bits[i];
    __syncthreads();

    int nvec16 = E >> 4;  // groups of 16 edges
    int stride = gridDim.x * blockDim.x;
    for (int g = blockIdx.x * blockDim.x + threadIdx.x; g < nvec16; g += stride) {
        int base = g * 16;
        // 12 independent streaming loads front-batched (bytes-in-flight)
        int4 s0 = __ldcs(reinterpret_cast<const int4*>(ei + base));
        int4 s1 = __ldcs(reinterpret_cast<const int4*>(ei + base + 4));
        int4 s2 = __ldcs(reinterpret_cast<const int4*>(ei + base + 8));
        int4 s3 = __ldcs(reinterpret_cast<const int4*>(ei + base + 12));
        int4 d0 = __ldcs(reinterpret_cast<const int4*>(ei + E + base));
        int4 d1 = __ldcs(reinterpret_cast<const int4*>(ei + E + base + 4));
        int4 d2 = __ldcs(reinterpret_cast<const int4*>(ei + E + base + 8));
        int4 d3 = __ldcs(reinterpret_cast<const int4*>(ei + E + base + 12));
        float4 v0 = __ldcs(reinterpret_cast<const float4*>(vals + base));
        float4 v1 = __ldcs(reinterpret_cast<const float4*>(vals + base + 4));
        float4 v2 = __ldcs(reinterpret_cast<const float4*>(vals + base + 8));
        float4 v3 = __ldcs(reinterpret_cast<const float4*>(vals + base + 12));

        float4 r0 = mask4(bits, s0, d0, v0);
        float4 r1 = mask4(bits, s1, d1, v1);
        float4 r2 = mask4(bits, s2, d2, v2);
        float4 r3 = mask4(bits, s3, d3, v3);

        __stcs(reinterpret_cast<float4*>(out + base),      r0);
        __stcs(reinterpret_cast<float4*>(out + base + 4),  r1);
        __stcs(reinterpret_cast<float4*>(out + base + 8),  r2);
        __stcs(reinterpret_cast<float4*>(out + base + 12), r3);
    }

    // scalar tail (E % 16 edges), block 0 thread 0
    if (blockIdx.x == 0 && threadIdx.x == 0) {
        for (int e = nvec16 * 16; e < E; ++e) {
            int s = ei[e];
            int d = ei[E + e];
            out[e] = (bit_of(bits, s) | bit_of(bits, d)) ? 0.0f : vals[e];
        }
    }
}

extern "C" void kernel_launch(void* const* d_in, const int* in_sizes, int n_in,
                              void* d_out, int out_size)
{
    const int*          ei    = (const int*)d_in[0];          // [2, E] int32
    const float*        vals  = (const float*)d_in[1];        // [E] float32
    const unsigned int* flags = (const unsigned int*)d_in[2]; // [N] 4-byte 0/nonzero
    float* out = (float*)d_out;

    int E = in_sizes[1];
    int N = in_sizes[2];
    int nwords = (N + 31) / 32;

    int num_sms = 0;
    cudaDeviceGetAttribute(&num_sms, cudaDevAttrMultiProcessorCount, 0);
    if (num_sms <= 0) num_sms = 148;

    size_t smem_bytes = (size_t)nwords * sizeof(unsigned int);
    cudaFuncSetAttribute(node_dropout_kernel,
                         cudaFuncAttributeMaxDynamicSharedMemorySize,
                         (int)smem_bytes);

    // 1) pack flags -> bitmask
    {
        int total_threads = nwords * 32;
        int threads = 256;
        int blocks = (total_threads + threads - 1) / threads;
        pack_flags_kernel<<<blocks, threads>>>(flags, N, nwords);
    }

    // 2) masked copy with smem-resident bitmask, one CTA per SM
    node_dropout_kernel<<<num_sms, 768, smem_bytes>>>(ei, vals, out, E, nwords);
}

// round 14
// speedup vs baseline: 1.1922x; 1.1922x over previous
#include <cuda_runtime.h>
#include <cstdint>

// NodeDropout: out[e] = values[e] unless src or dst node dropped.
// R8 operating point restored (measured best: 32 warps/SM, 8 edges/thread)
// + streaming cache hints as the single new variable.
// Evidence: per-warp delivery rate is constant across unrolls (1.93%/warp);
// throughput = warps x rate, warps maxed at 1024 threads / 1 CTA/SM.

#define MAX_BIT_WORDS 65536  // supports up to 2,097,152 nodes
__device__ unsigned int g_bits[MAX_BIT_WORDS];

// ---- pre-kernel: pack flags (4-byte 0/nonzero) into bitmask via ballot ----
__global__ void pack_flags_kernel(const unsigned int* __restrict__ flags,
                                  int N, int nwords)
{
    int t = blockIdx.x * blockDim.x + threadIdx.x;
    int w = t >> 5;
    int lane = t & 31;
    if (w >= nwords) return;
    int idx = w * 32 + lane;
    unsigned int f = (idx < N) ? flags[idx] : 0u;
    unsigned int ballot = __ballot_sync(0xFFFFFFFFu, f != 0u);
    if (lane == 0) g_bits[w] = ballot;
}

__device__ __forceinline__ unsigned int bit_of(const unsigned int* bits, int i)
{
    return (bits[i >> 5] >> (i & 31)) & 1u;
}

// ---- main kernel: one CTA/SM, bitmask in smem, 8 edges/thread/iter ----
__global__ void __launch_bounds__(1024, 1)
node_dropout_kernel(const int* __restrict__ ei,
                    const float* __restrict__ vals,
                    float* __restrict__ out,
                    int E, int nwords)
{
    extern __shared__ unsigned int bits[];
    for (int i = threadIdx.x; i < nwords; i += blockDim.x)
        bits[i] = g_bits[i];
    __syncthreads();

    int nvec8 = E >> 3;  // groups of 8 edges
    int stride = gridDim.x * blockDim.x;
    for (int g = blockIdx.x * blockDim.x + threadIdx.x; g < nvec8; g += stride) {
        int base = g * 8;
        // 6 independent streaming loads issued up front
        int4   sA = __ldcs(reinterpret_cast<const int4*>(ei + base));
        int4   sB = __ldcs(reinterpret_cast<const int4*>(ei + base + 4));
        int4   dA = __ldcs(reinterpret_cast<const int4*>(ei + E + base));
        int4   dB = __ldcs(reinterpret_cast<const int4*>(ei + E + base + 4));
        float4 vA = __ldcs(reinterpret_cast<const float4*>(vals + base));
        float4 vB = __ldcs(reinterpret_cast<const float4*>(vals + base + 4));

        float4 rA, rB;
        rA.x = (bit_of(bits, sA.x) | bit_of(bits, dA.x)) ? 0.0f : vA.x;
        rA.y = (bit_of(bits, sA.y) | bit_of(bits, dA.y)) ? 0.0f : vA.y;
        rA.z = (bit_of(bits, sA.z) | bit_of(bits, dA.z)) ? 0.0f : vA.z;
        rA.w = (bit_of(bits, sA.w) | bit_of(bits, dA.w)) ? 0.0f : vA.w;
        rB.x = (bit_of(bits, sB.x) | bit_of(bits, dB.x)) ? 0.0f : vB.x;
        rB.y = (bit_of(bits, sB.y) | bit_of(bits, dB.y)) ? 0.0f : vB.y;
        rB.z = (bit_of(bits, sB.z) | bit_of(bits, dB.z)) ? 0.0f : vB.z;
        rB.w = (bit_of(bits, sB.w) | bit_of(bits, dB.w)) ? 0.0f : vB.w;

        __stcs(reinterpret_cast<float4*>(out + base),     rA);
        __stcs(reinterpret_cast<float4*>(out + base + 4), rB);
    }

    // scalar tail (E % 8 edges), block 0 thread 0
    if (blockIdx.x == 0 && threadIdx.x == 0) {
        for (int e = nvec8 * 8; e < E; ++e) {
            int s = ei[e];
            int d = ei[E + e];
            out[e] = (bit_of(bits, s) | bit_of(bits, d)) ? 0.0f : vals[e];
        }
    }
}

extern "C" void kernel_launch(void* const* d_in, const int* in_sizes, int n_in,
                              void* d_out, int out_size)
{
    const int*          ei    = (const int*)d_in[0];          // [2, E] int32
    const float*        vals  = (const float*)d_in[1];        // [E] float32
    const unsigned int* flags = (const unsigned int*)d_in[2]; // [N] 4-byte 0/nonzero
    float* out = (float*)d_out;

    int E = in_sizes[1];
    int N = in_sizes[2];
    int nwords = (N + 31) / 32;

    int num_sms = 0;
    cudaDeviceGetAttribute(&num_sms, cudaDevAttrMultiProcessorCount, 0);
    if (num_sms <= 0) num_sms = 148;

    size_t smem_bytes = (size_t)nwords * sizeof(unsigned int);
    cudaFuncSetAttribute(node_dropout_kernel,
                         cudaFuncAttributeMaxDynamicSharedMemorySize,
                         (int)smem_bytes);

    // 1) pack flags -> bitmask
    {
        int total_threads = nwords * 32;
        int threads = 256;
        int blocks = (total_threads + threads - 1) / threads;
        pack_flags_kernel<<<blocks, threads>>>(flags, N, nwords);
    }

    // 2) masked copy with smem-resident bitmask, one CTA per SM
    node_dropout_kernel<<<num_sms, 1024, smem_bytes>>>(ei, vals, out, E, nwords);
}